// round 16
// baseline (speedup 1.0000x reference)
#include <cuda_runtime.h>
#include <cuda_bf16.h>
#include <cstdint>

// Problem constants
#define NN 50000
#define EE 1600000
#define ET (EE + NN)
#define DHD 128
#define PERM_SZ (NN + 3 * 128)
#define RB ((NN + 127) / 128)       // 391
#define SB ((PERM_SZ + 127) / 128)  // 396

// Dynamic smem (words): A[128][68] | Bfrag chunk [8][16][64]
#define SA_STRIDE 68
#define OFF_B (128 * SA_STRIDE)
#define GEMM_SMEM ((128 * SA_STRIDE + 8 * 16 * 64) * 4)  // 67584 B

// ---------------- device scratch ----------------
__device__ __nv_bfloat16 g_yX[(size_t)NN * 384];   // gated X-side messages (xz|xr|xh)
__device__ __nv_bfloat16 g_yH[(size_t)NN * 256];   // gated h-side messages (hz|hr)
__device__ __nv_bfloat16 g_yHH[(size_t)NN * 128];  // gated rh messages (hh)
__device__ float g_bufX[(size_t)NN * 384];   // gather results
__device__ float g_bufH[(size_t)NN * 256];
__device__ float g_bufX2[(size_t)NN * 384];  // self-GEMM results (separate: enables overlap)
__device__ float g_bufH2[(size_t)NN * 256];
__device__ float g_bufHH2[(size_t)NN * 128];
__device__ float g_WS[18 * DHD * DHD];       // per-conv per-role W@S (plain [k][n])
__device__ float g_gate[6 * 3 * DHD];        // sigmoid(Wg+bg) per conv/role
__device__ uint32_t g_Bimg[24 * DHD * DHD];  // tf32 fragment-ordered B images
__device__ int g_deg[NN];
__device__ int g_off[NN + 1];
__device__ int g_pos[NN];
__device__ int g_csr[ET];
__device__ int g_roleCnt[3];
__device__ int g_rolePadOff[4];
__device__ int g_rolePos[3];
__device__ int g_perm[PERM_SZ];

// ---------------- helpers ----------------
__device__ __forceinline__ uint32_t f2tf32(float x) {
    uint32_t r;
    asm("cvt.rna.tf32.f32 %0, %1;" : "=r"(r) : "f"(x));
    return r;
}
__device__ __forceinline__ void mma8(float* c, const uint32_t* a, uint2 b) {
    asm volatile(
        "mma.sync.aligned.m16n8k8.row.col.f32.tf32.tf32.f32 "
        "{%0,%1,%2,%3},{%4,%5,%6,%7},{%8,%9},{%0,%1,%2,%3};"
        : "+f"(c[0]), "+f"(c[1]), "+f"(c[2]), "+f"(c[3])
        : "r"(a[0]), "r"(a[1]), "r"(a[2]), "r"(a[3]), "r"(b.x), "r"(b.y));
}
__device__ __forceinline__ float sigm(float x) { return 1.0f / (1.0f + __expf(-x)); }
__device__ __forceinline__ float rl(float x) { return fmaxf(x, 0.f); }

// rh[gr, col..col+3] computed on the fly — MUST match the old combine_zr formula exactly.
__device__ __forceinline__ float4 rh_val4(int gr, int col, const float* __restrict__ h) {
    float4 xr = *(const float4*)(g_bufX + (size_t)gr * 384 + 128 + col);
    float4 xr2 = *(const float4*)(g_bufX2 + (size_t)gr * 384 + 128 + col);
    float4 hr = *(const float4*)(g_bufH + (size_t)gr * 256 + 128 + col);
    float4 hr2 = *(const float4*)(g_bufH2 + (size_t)gr * 256 + 128 + col);
    float4 hv = *(const float4*)(h + (size_t)gr * 128 + col);
    float4 o;
    o.x = sigm(rl(xr.x + xr2.x) + rl(hr.x + hr2.x)) * hv.x;
    o.y = sigm(rl(xr.y + xr2.y) + rl(hr.y + hr2.y)) * hv.y;
    o.z = sigm(rl(xr.z + xr2.z) + rl(hr.z + hr2.z)) * hv.z;
    o.w = sigm(rl(xr.w + xr2.w) + rl(hr.w + hr2.w)) * hv.w;
    return o;
}

// ---------------- preprocessing ----------------
__global__ void init_kernel() {
    int i = blockIdx.x * blockDim.x + threadIdx.x;
    if (i < NN) g_deg[i] = 0;
    if (i < 3) g_roleCnt[i] = 0;
    if (i < PERM_SZ) g_perm[i] = -1;
}

__global__ void count_kernel(const int* __restrict__ ei, const int* __restrict__ role) {
    int t = blockIdx.x * blockDim.x + threadIdx.x;
    int e4 = t * 4;
    if (e4 + 3 < EE) {
        int4 c4 = *(const int4*)(ei + EE + e4);
        atomicAdd(&g_deg[c4.x], 1);
        atomicAdd(&g_deg[c4.y], 1);
        atomicAdd(&g_deg[c4.z], 1);
        atomicAdd(&g_deg[c4.w], 1);
    } else {
        for (int e = e4; e < e4 + 4 && e < ET; e++) {
            int c = (e < EE) ? ei[EE + e] : (e - EE);
            atomicAdd(&g_deg[c], 1);
        }
    }
    int n4 = t * 4;
    if (n4 + 3 < NN) {
        int4 r4 = *(const int4*)(role + n4);
        atomicAdd(&g_roleCnt[r4.x], 1);
        atomicAdd(&g_roleCnt[r4.y], 1);
        atomicAdd(&g_roleCnt[r4.z], 1);
        atomicAdd(&g_roleCnt[r4.w], 1);
    } else {
        for (int n = n4; n < n4 + 4 && n < NN; n++) atomicAdd(&g_roleCnt[role[n]], 1);
    }
}

__global__ void scan_kernel() {
    __shared__ int warpsum[32];
    __shared__ int s_tot;
    __shared__ int s_carry;
    int t = threadIdx.x, lane = t & 31, w = t >> 5;
    if (t == 0) s_carry = 0;
    __syncthreads();
    for (int base = 0; base < NN; base += 1024) {
        int v = (base + t < NN) ? g_deg[base + t] : 0;
        int s = v;
#pragma unroll
        for (int o = 1; o < 32; o <<= 1) {
            int n = __shfl_up_sync(~0u, s, o);
            if (lane >= o) s += n;
        }
        if (lane == 31) warpsum[w] = s;
        __syncthreads();
        if (w == 0) {
            int ws = warpsum[lane];
            int t2 = ws;
#pragma unroll
            for (int o = 1; o < 32; o <<= 1) {
                int n = __shfl_up_sync(~0u, t2, o);
                if (lane >= o) t2 += n;
            }
            warpsum[lane] = t2 - ws;
            if (lane == 31) s_tot = t2;
        }
        __syncthreads();
        int excl = s_carry + warpsum[w] + s - v;
        if (base + t < NN) {
            g_off[base + t] = excl;
            g_pos[base + t] = excl;
        }
        __syncthreads();
        if (t == 0) s_carry += s_tot;
        __syncthreads();
    }
    if (t == 0) {
        g_off[NN] = s_carry;
        int o = 0;
        for (int r2 = 0; r2 < 3; r2++) {
            g_rolePadOff[r2] = o;
            g_rolePos[r2] = o;
            o += ((g_roleCnt[r2] + 127) >> 7) << 7;
        }
        g_rolePadOff[3] = o;
    }
}

__global__ void fill_kernel(const int* __restrict__ ei, const int* __restrict__ role) {
    int t = blockIdx.x * blockDim.x + threadIdx.x;
    int e4 = t * 4;
    if (e4 + 3 < EE) {
        int4 r4 = *(const int4*)(ei + e4);
        int4 c4 = *(const int4*)(ei + EE + e4);
        g_csr[atomicAdd(&g_pos[c4.x], 1)] = r4.x;
        g_csr[atomicAdd(&g_pos[c4.y], 1)] = r4.y;
        g_csr[atomicAdd(&g_pos[c4.z], 1)] = r4.z;
        g_csr[atomicAdd(&g_pos[c4.w], 1)] = r4.w;
    } else {
        for (int e = e4; e < e4 + 4 && e < ET; e++) {
            int r, c;
            if (e < EE) { r = ei[e]; c = ei[EE + e]; }
            else { r = e - EE; c = e - EE; }
            g_csr[atomicAdd(&g_pos[c], 1)] = r;
        }
    }
    int n4 = t * 4;
    if (n4 + 3 < NN) {
        int4 r4 = *(const int4*)(role + n4);
        g_perm[atomicAdd(&g_rolePos[r4.x], 1)] = n4;
        g_perm[atomicAdd(&g_rolePos[r4.y], 1)] = n4 + 1;
        g_perm[atomicAdd(&g_rolePos[r4.z], 1)] = n4 + 2;
        g_perm[atomicAdd(&g_rolePos[r4.w], 1)] = n4 + 3;
    } else {
        for (int n = n4; n < n4 + 4 && n < NN; n++)
            g_perm[atomicAdd(&g_rolePos[role[n]], 1)] = n;
    }
}

// gates: sigmoid(Wg + bg) for all 6 convs (order: xz,hz,xr,hr,xh,hh)
__global__ void gates_kernel(const float* g0, const float* b0, const float* g1, const float* b1,
                             const float* g2, const float* b2, const float* g3, const float* b3,
                             const float* g4, const float* b4, const float* g5, const float* b5) {
    int c = blockIdx.x, t = threadIdx.x;
    const float* gp;
    const float* bp;
    switch (c) {
        case 0: gp = g0; bp = b0; break;
        case 1: gp = g1; bp = b1; break;
        case 2: gp = g2; bp = b2; break;
        case 3: gp = g3; bp = b3; break;
        case 4: gp = g4; bp = b4; break;
        default: gp = g5; bp = b5; break;
    }
    float v = gp[t] + bp[t];
    g_gate[c * 384 + t] = 1.0f / (1.0f + __expf(-v));
}

// ---------------- WS[conv][r] = W @ S[r] (fp32 exact, tiny) ----------------
__global__ void __launch_bounds__(256) ws_all_kernel(
    const float* W0, const float* S0, const float* W1, const float* S1,
    const float* W2, const float* S2, const float* W3, const float* S3,
    const float* W4, const float* S4, const float* W5, const float* S5) {
    int conv = blockIdx.z, r = blockIdx.y, ct = blockIdx.x;
    const float* W;
    const float* S;
    switch (conv) {
        case 0: W = W0; S = S0; break;
        case 1: W = W1; S = S1; break;
        case 2: W = W2; S = S2; break;
        case 3: W = W3; S = S3; break;
        case 4: W = W4; S = S4; break;
        default: W = W5; S = S5; break;
    }
    const float* B = S + ((size_t)r << 14) + ct * 32;
    float* C = g_WS + (((size_t)conv * 3 + r) << 14) + ct * 32;

    __shared__ float As[DHD][33];
    __shared__ float Bs[32][33];
    int tid = threadIdx.x;
    int tr = tid >> 4, tc = tid & 15;
    float acc[8][2] = {};
    for (int kc = 0; kc < DHD; kc += 32) {
#pragma unroll
        for (int t = 0; t < 4; t++) {
            int idx = tid + t * 256;
            int row = idx >> 3;
            int kq = (idx & 7) << 2;
            float4 v = *(const float4*)&W[(size_t)row * DHD + kc + kq];
            As[row][kq] = v.x; As[row][kq + 1] = v.y; As[row][kq + 2] = v.z; As[row][kq + 3] = v.w;
        }
#pragma unroll
        for (int t = 0; t < 4; t++) {
            int idx = tid + t * 256;
            int kk = idx >> 5;
            int j = idx & 31;
            Bs[kk][j] = B[(size_t)(kc + kk) * DHD + j];
        }
        __syncthreads();
#pragma unroll 8
        for (int kk = 0; kk < 32; kk++) {
            float b0 = Bs[kk][tc * 2], b1 = Bs[kk][tc * 2 + 1];
#pragma unroll
            for (int i = 0; i < 8; i++) {
                float a = As[tr * 8 + i][kk];
                acc[i][0] += a * b0;
                acc[i][1] += a * b1;
            }
        }
        __syncthreads();
    }
#pragma unroll
    for (int i = 0; i < 8; i++) {
        C[(size_t)(tr * 8 + i) * DHD + tc * 2] = acc[i][0];
        C[(size_t)(tr * 8 + i) * DHD + tc * 2 + 1] = acc[i][1];
    }
}

// ---------------- build tf32 fragment-ordered B images ----------------
__global__ void __launch_bounds__(256) img_kernel(const float* W0, const float* W1,
                                                  const float* W2, const float* W3,
                                                  const float* W4, const float* W5) {
    int m = blockIdx.x;
    const float* src;
    switch (m) {
        case 0: src = W0; break;
        case 1: src = W1; break;
        case 2: src = W2; break;
        case 3: src = W3; break;
        case 4: src = W4; break;
        case 5: src = W5; break;
        default: src = g_WS + (size_t)(m - 6) * 16384; break;
    }
    uint32_t* dst = g_Bimg + (size_t)m * 16384;
    for (int i = threadIdx.x; i < 16384; i += 256) {
        int l2 = i & 63;
        int nt = (i >> 6) & 15;
        int kit = i >> 10;
        int lane = l2 >> 1, half = l2 & 1;
        int k = kit * 8 + (lane & 3) + half * 4;
        int n = nt * 8 + (lane >> 2);
        dst[i] = f2tf32(src[k * DHD + n]);
    }
}

// ---------------- tf32 tensor-core GEMM mainloop (single-pass A) ----------------
// rhMode: A-operand is rh computed on the fly from gather/self buffers + h.
__device__ __forceinline__ void gemm_mainloop(float (*acc)[8][4], uint32_t* sm,
                                              const float* __restrict__ Xp,
                                              const int* rows, int matIdx, int tid,
                                              int rhMode) {
    int lane = tid & 31, wid = tid >> 5;
    int warp_m = wid & 3, warp_n = wid >> 2;
    uint32_t* sA = sm;
    uint32_t* sB = sm + OFF_B;

    for (int kc = 0; kc < 2; kc++) {
        if (kc) __syncthreads();
#pragma unroll
        for (int it = 0; it < 8; it++) {
            int i = tid + it * 256;
            int row = i >> 4, f4 = i & 15;
            int gr = rows[row];
            float4 v = make_float4(0.f, 0.f, 0.f, 0.f);
            if (gr >= 0) {
                if (rhMode)
                    v = rh_val4(gr, kc * 64 + f4 * 4, Xp);
                else
                    v = *(const float4*)(Xp + (size_t)gr * DHD + kc * 64 + f4 * 4);
            }
            int base = row * SA_STRIDE + f4 * 4;
            *(uint4*)(sA + base) = make_uint4(f2tf32(v.x), f2tf32(v.y), f2tf32(v.z), f2tf32(v.w));
        }
        const uint4* bsrc = (const uint4*)(g_Bimg + (size_t)matIdx * 16384 + kc * 8192);
#pragma unroll
        for (int it = 0; it < 8; it++) {
            ((uint4*)sB)[tid + it * 256] = bsrc[tid + it * 256];
        }
        __syncthreads();

#pragma unroll
        for (int kit = 0; kit < 8; kit++) {
            uint32_t ah[2][4];
#pragma unroll
            for (int mt = 0; mt < 2; mt++) {
                int r0 = warp_m * 32 + mt * 16 + (lane >> 2);
                int kk = kit * 8 + (lane & 3);
                ah[mt][0] = sA[r0 * SA_STRIDE + kk];
                ah[mt][1] = sA[(r0 + 8) * SA_STRIDE + kk];
                ah[mt][2] = sA[r0 * SA_STRIDE + kk + 4];
                ah[mt][3] = sA[(r0 + 8) * SA_STRIDE + kk + 4];
            }
#pragma unroll
            for (int nt = 0; nt < 8; nt++) {
                int gnt = warp_n * 8 + nt;
                uint2 b = *(uint2*)(sB + (kit * 16 + gnt) * 64 + lane * 2);
#pragma unroll
                for (int mt = 0; mt < 2; mt++) {
                    mma8(acc[mt][nt], ah[mt], b);
                }
            }
        }
    }
}

#define DECL_ACC(acc)                     \
    float acc[2][8][4];                   \
    _Pragma("unroll") for (int _a = 0; _a < 2; _a++) _Pragma("unroll") for (int _b = 0;        \
                                                                            _b < 8; _b++)      \
        _Pragma("unroll") for (int _c = 0; _c < 4; _c++) acc[_a][_b][_c] = 0.f;

// ---------------- fused Y GEMMs (bf16 output) ----------------
// mode 0: X -> g_yX [N,384], convs {0,2,4}, with bias
// mode 1: h -> g_yH [N,256], convs {1,3}
// mode 2: rh(on-the-fly from h=Aext) -> g_yHH [N,128], conv 5
__global__ void __launch_bounds__(256) gemm_y_f(const float* __restrict__ Aext, int mode,
                                                const float* __restrict__ bxz,
                                                const float* __restrict__ bxr,
                                                const float* __restrict__ bxh,
                                                const int* __restrict__ role) {
    extern __shared__ __align__(16) uint32_t sm[];
    __shared__ float sg[DHD * 3];
    __shared__ float bb[DHD * 3];
    __shared__ int role_s[DHD];
    __shared__ int rows[DHD];

    int tid = threadIdx.x, ct = blockIdx.y;
    int r0 = blockIdx.x * DHD;

    int conv, ostride;
    __nv_bfloat16* obase;
    const float* bvec = nullptr;
    if (mode == 0) {
        conv = ct * 2;
        ostride = 384;
        obase = g_yX;
        bvec = (ct == 0) ? bxz : ((ct == 1) ? bxr : bxh);
    } else if (mode == 1) {
        conv = 1 + ct * 2;
        ostride = 256;
        obase = g_yH;
    } else {
        conv = 5;
        ostride = 128;
        obase = g_yHH;
    }

    for (int t = tid; t < 3 * DHD; t += 256) {
        sg[t] = g_gate[conv * 384 + t];
        bb[t] = bvec ? bvec[t] : 0.0f;
    }
    if (tid < DHD) {
        int gr = r0 + tid;
        rows[tid] = (gr < NN) ? gr : -1;
        role_s[tid] = (gr < NN) ? role[gr] : 0;
    }
    __syncthreads();

    DECL_ACC(acc)
    gemm_mainloop(acc, sm, Aext, rows, conv, tid, mode == 2 ? 1 : 0);

    int lane = tid & 31, wid = tid >> 5;
    int warp_m = wid & 3, warp_n = wid >> 2;
#pragma unroll
    for (int mt = 0; mt < 2; mt++) {
#pragma unroll
        for (int h = 0; h < 2; h++) {
            int lrow = warp_m * 32 + mt * 16 + (lane >> 2) + h * 8;
            int grow = r0 + lrow;
            if (grow >= NN) continue;
            int rb = role_s[lrow] * 128;
            __nv_bfloat16* yp = obase + (size_t)grow * ostride + ct * 128;
#pragma unroll
            for (int nt = 0; nt < 8; nt++) {
                int col = warp_n * 64 + nt * 8 + (lane & 3) * 2;
                float v0 = acc[mt][nt][h * 2] * sg[rb + col] + bb[rb + col];
                float v1 = acc[mt][nt][h * 2 + 1] * sg[rb + col + 1] + bb[rb + col + 1];
                *(__nv_bfloat162*)(yp + col) = __float22bfloat162_rn(make_float2(v0, v1));
            }
        }
    }
}

// ---------------- fused self GEMMs: buf2 = A[node] @ WS[conv][role] (overwrite) -----
__global__ void __launch_bounds__(256) gemm_self_f(const float* __restrict__ Aext, int mode) {
    int rowBase = blockIdx.x * DHD;
    if (rowBase >= g_rolePadOff[3]) return;
    extern __shared__ __align__(16) uint32_t sm[];
    __shared__ int rows[DHD];

    int tid = threadIdx.x, ct = blockIdx.y;

    int r = 0;
    if (rowBase >= g_rolePadOff[1]) r = 1;
    if (rowBase >= g_rolePadOff[2]) r = 2;

    int conv, ostride;
    float* obase;
    if (mode == 0) { conv = ct * 2; ostride = 384; obase = g_bufX2; }
    else if (mode == 1) { conv = 1 + ct * 2; ostride = 256; obase = g_bufH2; }
    else { conv = 5; ostride = 128; obase = g_bufHH2; }
    int matIdx = 6 + conv * 3 + r;

    if (tid < DHD) rows[tid] = (rowBase + tid < PERM_SZ) ? g_perm[rowBase + tid] : -1;
    __syncthreads();

    DECL_ACC(acc)
    gemm_mainloop(acc, sm, Aext, rows, matIdx, tid, mode == 2 ? 1 : 0);

    int lane = tid & 31, wid = tid >> 5;
    int warp_m = wid & 3, warp_n = wid >> 2;
#pragma unroll
    for (int mt = 0; mt < 2; mt++) {
#pragma unroll
        for (int h = 0; h < 2; h++) {
            int lrow = warp_m * 32 + mt * 16 + (lane >> 2) + h * 8;
            int node = rows[lrow];
            if (node < 0) continue;
            float* cp = obase + (size_t)node * ostride + ct * 128;
#pragma unroll
            for (int nt = 0; nt < 8; nt++) {
                int col = warp_n * 64 + nt * 8 + (lane & 3) * 2;
                *(float2*)(cp + col) =
                    make_float2(acc[mt][nt][h * 2], acc[mt][nt][h * 2 + 1]);
            }
        }
    }
}

// ---------------- fused gathers (warp per node) ----------------
__device__ __forceinline__ void bfacc(float4& a, uint2 u) {
    float2 f0 = __bfloat1622float2(*(__nv_bfloat162*)&u.x);
    float2 f1 = __bfloat1622float2(*(__nv_bfloat162*)&u.y);
    a.x += f0.x; a.y += f0.y; a.z += f1.x; a.w += f1.y;
}
__device__ __forceinline__ float4 scale4(float4 a, float s) {
    return make_float4(a.x * s, a.y * s, a.z * s, a.w * s);
}

// combined gather over yX (3 segs) and yH (2 segs) — MLP 5 (proven best form)
__global__ void __launch_bounds__(256) gather_xh_kernel() {
    int w = (blockIdx.x * blockDim.x + threadIdx.x) >> 5;
    int lane = threadIdx.x & 31;
    if (w >= NN) return;
    int s = g_off[w], e = g_off[w + 1];
    float4 a[5];
#pragma unroll
    for (int q = 0; q < 5; q++) a[q] = make_float4(0.f, 0.f, 0.f, 0.f);
    for (int p = s; p < e; p++) {
        int s0 = g_csr[p];
        const uint2* bx = (const uint2*)(g_yX + (size_t)s0 * 384);
        const uint2* bh = (const uint2*)(g_yH + (size_t)s0 * 256);
        uint2 u[5];
#pragma unroll
        for (int q = 0; q < 3; q++) u[q] = bx[lane + q * 32];
#pragma unroll
        for (int q = 0; q < 2; q++) u[3 + q] = bh[lane + q * 32];
#pragma unroll
        for (int q = 0; q < 5; q++) bfacc(a[q], u[q]);
    }
    float inv = 1.0f / (float)(e - s);
    float* ox = g_bufX + (size_t)w * 384;
    float* oh = g_bufH + (size_t)w * 256;
#pragma unroll
    for (int q = 0; q < 3; q++) *(float4*)(ox + q * 128 + lane * 4) = scale4(a[q], inv);
#pragma unroll
    for (int q = 0; q < 2; q++) *(float4*)(oh + q * 128 + lane * 4) = scale4(a[3 + q], inv);
}

// fused: gather yHH (mean) + z computed inline + final GRU combine -> out.
__global__ void __launch_bounds__(256) gather_hh_combine_kernel(const float* __restrict__ h,
                                                                float* __restrict__ out) {
    int w = (blockIdx.x * blockDim.x + threadIdx.x) >> 5;
    int lane = threadIdx.x & 31;
    if (w >= NN) return;
    int s = g_off[w], e = g_off[w + 1];
    float4 a0 = make_float4(0.f, 0.f, 0.f, 0.f);
    float4 a1 = make_float4(0.f, 0.f, 0.f, 0.f);
    int p = s;
    for (; p + 2 <= e; p += 2) {
        int s0 = g_csr[p], s1v = g_csr[p + 1];
        uint2 u0 = ((const uint2*)(g_yHH + (size_t)s0 * 128))[lane];
        uint2 u1 = ((const uint2*)(g_yHH + (size_t)s1v * 128))[lane];
        bfacc(a0, u0);
        bfacc(a1, u1);
    }
    if (p < e) {
        uint2 u0 = ((const uint2*)(g_yHH + (size_t)g_csr[p] * 128))[lane];
        bfacc(a0, u0);
    }
    float inv = 1.0f / (float)(e - s);
    a0.x += a1.x; a0.y += a1.y; a0.z += a1.z; a0.w += a1.w;
    float4 hh = scale4(a0, inv);

    int col = lane * 4;
    size_t base = (size_t)w * 128 + col;
    float4 hh2 = *(const float4*)(g_bufHH2 + base);
    float4 xh = *(const float4*)(g_bufX + (size_t)w * 384 + 256 + col);
    float4 xh2 = *(const float4*)(g_bufX2 + (size_t)w * 384 + 256 + col);
    // z computed inline (was combine_zr)
    float4 xz = *(const float4*)(g_bufX + (size_t)w * 384 + col);
    float4 xz2 = *(const float4*)(g_bufX2 + (size_t)w * 384 + col);
    float4 hz = *(const float4*)(g_bufH + (size_t)w * 256 + col);
    float4 hz2 = *(const float4*)(g_bufH2 + (size_t)w * 256 + col);
    float4 hv = *(const float4*)(h + base);
    float4 zv;
    zv.x = sigm(rl(xz.x + xz2.x) + rl(hz.x + hz2.x));
    zv.y = sigm(rl(xz.y + xz2.y) + rl(hz.y + hz2.y));
    zv.z = sigm(rl(xz.z + xz2.z) + rl(hz.z + hz2.z));
    zv.w = sigm(rl(xz.w + xz2.w) + rl(hz.w + hz2.w));

    float4 o;
    float t;
    t = tanhf(rl(xh.x + xh2.x) + rl(hh.x + hh2.x)); o.x = zv.x * hv.x + (1.f - zv.x) * t;
    t = tanhf(rl(xh.y + xh2.y) + rl(hh.y + hh2.y)); o.y = zv.y * hv.y + (1.f - zv.y) * t;
    t = tanhf(rl(xh.z + xh2.z) + rl(hh.z + hh2.z)); o.z = zv.z * hv.z + (1.f - zv.z) * t;
    t = tanhf(rl(xh.w + xh2.w) + rl(hh.w + hh2.w)); o.w = zv.w * hv.w + (1.f - zv.w) * t;
    *(float4*)(out + base) = o;
}

// ---------------- host launch ----------------
extern "C" void kernel_launch(void* const* d_in, const int* in_sizes, int n_in,
                              void* d_out, int out_size) {
    cudaFuncSetAttribute(gemm_y_f, cudaFuncAttributeMaxDynamicSharedMemorySize, GEMM_SMEM);
    cudaFuncSetAttribute(gemm_self_f, cudaFuncAttributeMaxDynamicSharedMemorySize, GEMM_SMEM);

    // Default-priority side stream (low priority starved the critical CSR branch in R15).
    static cudaStream_t s1 = nullptr;
    static cudaEvent_t evF = nullptr, evA = nullptr, evB = nullptr, evC = nullptr,
                       evD = nullptr, evE = nullptr;
    if (!s1) {
        cudaStreamCreateWithFlags(&s1, cudaStreamNonBlocking);
        cudaEventCreateWithFlags(&evF, cudaEventDisableTiming);
        cudaEventCreateWithFlags(&evA, cudaEventDisableTiming);
        cudaEventCreateWithFlags(&evB, cudaEventDisableTiming);
        cudaEventCreateWithFlags(&evC, cudaEventDisableTiming);
        cudaEventCreateWithFlags(&evD, cudaEventDisableTiming);
        cudaEventCreateWithFlags(&evE, cudaEventDisableTiming);
    }

    int iEdge = 2, iH = 1;
    if (in_sizes[1] == 2 * EE) { iEdge = 1; iH = 2; }
    const float* x = (const float*)d_in[0];
    const float* h_prev = (const float*)d_in[iH];
    const int* ei = (const int*)d_in[iEdge];
    const int* role = (const int*)d_in[3];

    const float* P[27];
    for (int i = 0; i < 27 && (4 + i) < n_in; i++) P[i] = (const float*)d_in[4 + i];
    // xz: W,Wg,bg,S,b = P0..P4 | hz: P5..P8 | xr: P9..P13 | hr: P14..P17
    // xh: P18..P22 | hh: P23..P26
    float* out = (float*)d_out;

    int warpGrid = (NN * 32 + 255) / 256;
    int e4Grid = (ET / 4 + 256) / 256 + 1;

    // ---- Fork 1: CSR build (s1) || weight prep + Y GEMMs (main) ----
    cudaEventRecord(evF, 0);
    cudaStreamWaitEvent(s1, evF, 0);
    init_kernel<<<(PERM_SZ + 255) / 256, 256, 0, s1>>>();
    count_kernel<<<e4Grid, 256, 0, s1>>>(ei, role);
    scan_kernel<<<1, 1024, 0, s1>>>();
    fill_kernel<<<e4Grid, 256, 0, s1>>>(ei, role);
    cudaEventRecord(evA, s1);

    gates_kernel<<<6, 384>>>(P[1], P[2], P[6], P[7], P[10], P[11], P[15], P[16], P[19], P[20],
                             P[24], P[25]);
    ws_all_kernel<<<dim3(4, 3, 6), 256>>>(P[0], P[3], P[5], P[8], P[9], P[12], P[14], P[17],
                                          P[18], P[21], P[23], P[26]);
    img_kernel<<<24, 256>>>(P[0], P[5], P[9], P[14], P[18], P[23]);
    gemm_y_f<<<dim3(RB, 3), 256, GEMM_SMEM>>>(x, 0, P[4], P[13], P[22], role);
    gemm_y_f<<<dim3(RB, 2), 256, GEMM_SMEM>>>(h_prev, 1, nullptr, nullptr, nullptr, role);
    cudaStreamWaitEvent(0, evA, 0);  // join: CSR ready

    // ---- Fork 2: gather (main, critical) || self GEMMs (s1) ----
    cudaEventRecord(evB, 0);
    cudaStreamWaitEvent(s1, evB, 0);
    gemm_self_f<<<dim3(SB, 3), 256, GEMM_SMEM, s1>>>(x, 0);
    gemm_self_f<<<dim3(SB, 2), 256, GEMM_SMEM, s1>>>(h_prev, 1);
    cudaEventRecord(evC, s1);
    gather_xh_kernel<<<warpGrid, 256>>>();
    cudaStreamWaitEvent(0, evC, 0);  // join (gather + self results both ready)

    // ---- Fork 3: self_hh (s1) || yHH GEMM (main), both with on-the-fly rh ----
    cudaEventRecord(evD, 0);
    cudaStreamWaitEvent(s1, evD, 0);
    gemm_self_f<<<dim3(SB, 1), 256, GEMM_SMEM, s1>>>(h_prev, 2);
    cudaEventRecord(evE, s1);
    gemm_y_f<<<dim3(RB, 1), 256, GEMM_SMEM>>>(h_prev, 2, nullptr, nullptr, nullptr, role);
    cudaStreamWaitEvent(0, evE, 0);  // join: self_hh done
    gather_hh_combine_kernel<<<warpGrid, 256>>>(h_prev, out);
}

// round 17
// speedup vs baseline: 1.0370x; 1.0370x over previous
#include <cuda_runtime.h>
#include <cuda_bf16.h>
#include <cstdint>

// Problem constants
#define NN 50000
#define EE 1600000
#define ET (EE + NN)
#define DHD 128
#define PERM_SZ (NN + 3 * 128)
#define RB ((NN + 127) / 128)       // 391
#define SB ((PERM_SZ + 127) / 128)  // 396

// Dynamic smem (words): A[128][68] | Bfrag chunk [8][16][64]
#define SA_STRIDE 68
#define OFF_B (128 * SA_STRIDE)
#define GEMM_SMEM ((128 * SA_STRIDE + 8 * 16 * 64) * 4)  // 67584 B

// Fused Y/buf column layout (width 640):
//   [0,128)=xz  [128,256)=xr  [256,384)=xh  [384,512)=hz  [512,640)=hr
#define YW 640

// ---------------- device scratch ----------------
__device__ __nv_bfloat16 g_Y[(size_t)NN * YW];     // fused gated messages
__device__ __nv_bfloat16 g_yHH[(size_t)NN * 128];  // gated rh messages (hh)
__device__ float g_buf[(size_t)NN * YW];           // gather results (fused layout)
__device__ float g_buf2[(size_t)NN * YW];          // self-GEMM results (fused layout)
__device__ float g_bufHH2[(size_t)NN * 128];
__device__ float g_z[(size_t)NN * DHD];
__device__ float g_rh[(size_t)NN * DHD];
__device__ float g_WS[18 * DHD * DHD];       // per-conv per-role W@S (plain [k][n])
__device__ float g_gate[6 * 3 * DHD];        // sigmoid(Wg+bg) per conv/role
__device__ uint32_t g_Bimg[24 * DHD * DHD];  // tf32 fragment-ordered B images
__device__ int g_deg[NN];
__device__ int g_off[NN + 1];
__device__ int g_pos[NN];
__device__ int g_csr[ET];
__device__ int g_roleCnt[3];
__device__ int g_rolePadOff[4];
__device__ int g_rolePos[3];
__device__ int g_perm[PERM_SZ];

// ---------------- helpers ----------------
__device__ __forceinline__ uint32_t f2tf32(float x) {
    uint32_t r;
    asm("cvt.rna.tf32.f32 %0, %1;" : "=r"(r) : "f"(x));
    return r;
}
__device__ __forceinline__ void mma8(float* c, const uint32_t* a, uint2 b) {
    asm volatile(
        "mma.sync.aligned.m16n8k8.row.col.f32.tf32.tf32.f32 "
        "{%0,%1,%2,%3},{%4,%5,%6,%7},{%8,%9},{%0,%1,%2,%3};"
        : "+f"(c[0]), "+f"(c[1]), "+f"(c[2]), "+f"(c[3])
        : "r"(a[0]), "r"(a[1]), "r"(a[2]), "r"(a[3]), "r"(b.x), "r"(b.y));
}
__device__ __forceinline__ float sigm(float x) { return 1.0f / (1.0f + __expf(-x)); }
__device__ __forceinline__ float rl(float x) { return fmaxf(x, 0.f); }

// ---------------- preprocessing ----------------
__global__ void init_kernel() {
    int i = blockIdx.x * blockDim.x + threadIdx.x;
    if (i < NN) g_deg[i] = 0;
    if (i < 3) g_roleCnt[i] = 0;
    if (i < PERM_SZ) g_perm[i] = -1;
}

__global__ void count_kernel(const int* __restrict__ ei, const int* __restrict__ role) {
    int t = blockIdx.x * blockDim.x + threadIdx.x;
    int e4 = t * 4;
    if (e4 + 3 < EE) {
        int4 c4 = *(const int4*)(ei + EE + e4);
        atomicAdd(&g_deg[c4.x], 1);
        atomicAdd(&g_deg[c4.y], 1);
        atomicAdd(&g_deg[c4.z], 1);
        atomicAdd(&g_deg[c4.w], 1);
    } else {
        for (int e = e4; e < e4 + 4 && e < ET; e++) {
            int c = (e < EE) ? ei[EE + e] : (e - EE);
            atomicAdd(&g_deg[c], 1);
        }
    }
    int n4 = t * 4;
    if (n4 + 3 < NN) {
        int4 r4 = *(const int4*)(role + n4);
        atomicAdd(&g_roleCnt[r4.x], 1);
        atomicAdd(&g_roleCnt[r4.y], 1);
        atomicAdd(&g_roleCnt[r4.z], 1);
        atomicAdd(&g_roleCnt[r4.w], 1);
    } else {
        for (int n = n4; n < n4 + 4 && n < NN; n++) atomicAdd(&g_roleCnt[role[n]], 1);
    }
}

__global__ void scan_kernel() {
    __shared__ int warpsum[32];
    __shared__ int s_tot;
    __shared__ int s_carry;
    int t = threadIdx.x, lane = t & 31, w = t >> 5;
    if (t == 0) s_carry = 0;
    __syncthreads();
    for (int base = 0; base < NN; base += 1024) {
        int v = (base + t < NN) ? g_deg[base + t] : 0;
        int s = v;
#pragma unroll
        for (int o = 1; o < 32; o <<= 1) {
            int n = __shfl_up_sync(~0u, s, o);
            if (lane >= o) s += n;
        }
        if (lane == 31) warpsum[w] = s;
        __syncthreads();
        if (w == 0) {
            int ws = warpsum[lane];
            int t2 = ws;
#pragma unroll
            for (int o = 1; o < 32; o <<= 1) {
                int n = __shfl_up_sync(~0u, t2, o);
                if (lane >= o) t2 += n;
            }
            warpsum[lane] = t2 - ws;
            if (lane == 31) s_tot = t2;
        }
        __syncthreads();
        int excl = s_carry + warpsum[w] + s - v;
        if (base + t < NN) {
            g_off[base + t] = excl;
            g_pos[base + t] = excl;
        }
        __syncthreads();
        if (t == 0) s_carry += s_tot;
        __syncthreads();
    }
    if (t == 0) {
        g_off[NN] = s_carry;
        int o = 0;
        for (int r2 = 0; r2 < 3; r2++) {
            g_rolePadOff[r2] = o;
            g_rolePos[r2] = o;
            o += ((g_roleCnt[r2] + 127) >> 7) << 7;
        }
        g_rolePadOff[3] = o;
    }
}

__global__ void fill_kernel(const int* __restrict__ ei, const int* __restrict__ role) {
    int t = blockIdx.x * blockDim.x + threadIdx.x;
    int e4 = t * 4;
    if (e4 + 3 < EE) {
        int4 r4 = *(const int4*)(ei + e4);
        int4 c4 = *(const int4*)(ei + EE + e4);
        g_csr[atomicAdd(&g_pos[c4.x], 1)] = r4.x;
        g_csr[atomicAdd(&g_pos[c4.y], 1)] = r4.y;
        g_csr[atomicAdd(&g_pos[c4.z], 1)] = r4.z;
        g_csr[atomicAdd(&g_pos[c4.w], 1)] = r4.w;
    } else {
        for (int e = e4; e < e4 + 4 && e < ET; e++) {
            int r, c;
            if (e < EE) { r = ei[e]; c = ei[EE + e]; }
            else { r = e - EE; c = e - EE; }
            g_csr[atomicAdd(&g_pos[c], 1)] = r;
        }
    }
    int n4 = t * 4;
    if (n4 + 3 < NN) {
        int4 r4 = *(const int4*)(role + n4);
        g_perm[atomicAdd(&g_rolePos[r4.x], 1)] = n4;
        g_perm[atomicAdd(&g_rolePos[r4.y], 1)] = n4 + 1;
        g_perm[atomicAdd(&g_rolePos[r4.z], 1)] = n4 + 2;
        g_perm[atomicAdd(&g_rolePos[r4.w], 1)] = n4 + 3;
    } else {
        for (int n = n4; n < n4 + 4 && n < NN; n++)
            g_perm[atomicAdd(&g_rolePos[role[n]], 1)] = n;
    }
}

// gates: sigmoid(Wg + bg) for all 6 convs (order: xz,hz,xr,hr,xh,hh)
__global__ void gates_kernel(const float* g0, const float* b0, const float* g1, const float* b1,
                             const float* g2, const float* b2, const float* g3, const float* b3,
                             const float* g4, const float* b4, const float* g5, const float* b5) {
    int c = blockIdx.x, t = threadIdx.x;
    const float* gp;
    const float* bp;
    switch (c) {
        case 0: gp = g0; bp = b0; break;
        case 1: gp = g1; bp = b1; break;
        case 2: gp = g2; bp = b2; break;
        case 3: gp = g3; bp = b3; break;
        case 4: gp = g4; bp = b4; break;
        default: gp = g5; bp = b5; break;
    }
    float v = gp[t] + bp[t];
    g_gate[c * 384 + t] = 1.0f / (1.0f + __expf(-v));
}

// ---------------- WS[conv][r] = W @ S[r] (fp32 exact, tiny) ----------------
__global__ void __launch_bounds__(256) ws_all_kernel(
    const float* W0, const float* S0, const float* W1, const float* S1,
    const float* W2, const float* S2, const float* W3, const float* S3,
    const float* W4, const float* S4, const float* W5, const float* S5) {
    int conv = blockIdx.z, r = blockIdx.y, ct = blockIdx.x;
    const float* W;
    const float* S;
    switch (conv) {
        case 0: W = W0; S = S0; break;
        case 1: W = W1; S = S1; break;
        case 2: W = W2; S = S2; break;
        case 3: W = W3; S = S3; break;
        case 4: W = W4; S = S4; break;
        default: W = W5; S = S5; break;
    }
    const float* B = S + ((size_t)r << 14) + ct * 32;
    float* C = g_WS + (((size_t)conv * 3 + r) << 14) + ct * 32;

    __shared__ float As[DHD][33];
    __shared__ float Bs[32][33];
    int tid = threadIdx.x;
    int tr = tid >> 4, tc = tid & 15;
    float acc[8][2] = {};
    for (int kc = 0; kc < DHD; kc += 32) {
#pragma unroll
        for (int t = 0; t < 4; t++) {
            int idx = tid + t * 256;
            int row = idx >> 3;
            int kq = (idx & 7) << 2;
            float4 v = *(const float4*)&W[(size_t)row * DHD + kc + kq];
            As[row][kq] = v.x; As[row][kq + 1] = v.y; As[row][kq + 2] = v.z; As[row][kq + 3] = v.w;
        }
#pragma unroll
        for (int t = 0; t < 4; t++) {
            int idx = tid + t * 256;
            int kk = idx >> 5;
            int j = idx & 31;
            Bs[kk][j] = B[(size_t)(kc + kk) * DHD + j];
        }
        __syncthreads();
#pragma unroll 8
        for (int kk = 0; kk < 32; kk++) {
            float b0 = Bs[kk][tc * 2], b1 = Bs[kk][tc * 2 + 1];
#pragma unroll
            for (int i = 0; i < 8; i++) {
                float a = As[tr * 8 + i][kk];
                acc[i][0] += a * b0;
                acc[i][1] += a * b1;
            }
        }
        __syncthreads();
    }
#pragma unroll
    for (int i = 0; i < 8; i++) {
        C[(size_t)(tr * 8 + i) * DHD + tc * 2] = acc[i][0];
        C[(size_t)(tr * 8 + i) * DHD + tc * 2 + 1] = acc[i][1];
    }
}

// ---------------- build tf32 fragment-ordered B images ----------------
__global__ void __launch_bounds__(256) img_kernel(const float* W0, const float* W1,
                                                  const float* W2, const float* W3,
                                                  const float* W4, const float* W5) {
    int m = blockIdx.x;
    const float* src;
    switch (m) {
        case 0: src = W0; break;
        case 1: src = W1; break;
        case 2: src = W2; break;
        case 3: src = W3; break;
        case 4: src = W4; break;
        case 5: src = W5; break;
        default: src = g_WS + (size_t)(m - 6) * 16384; break;
    }
    uint32_t* dst = g_Bimg + (size_t)m * 16384;
    for (int i = threadIdx.x; i < 16384; i += 256) {
        int l2 = i & 63;
        int nt = (i >> 6) & 15;
        int kit = i >> 10;
        int lane = l2 >> 1, half = l2 & 1;
        int k = kit * 8 + (lane & 3) + half * 4;
        int n = nt * 8 + (lane >> 2);
        dst[i] = f2tf32(src[k * DHD + n]);
    }
}

// ---------------- tf32 tensor-core GEMM mainloop (single-pass A) ----------------
__device__ __forceinline__ void gemm_mainloop(float (*acc)[8][4], uint32_t* sm,
                                              const float* __restrict__ Xp,
                                              const int* rows, int matIdx, int tid) {
    int lane = tid & 31, wid = tid >> 5;
    int warp_m = wid & 3, warp_n = wid >> 2;
    uint32_t* sA = sm;
    uint32_t* sB = sm + OFF_B;

    for (int kc = 0; kc < 2; kc++) {
        if (kc) __syncthreads();
#pragma unroll
        for (int it = 0; it < 8; it++) {
            int i = tid + it * 256;
            int row = i >> 4, f4 = i & 15;
            int gr = rows[row];
            float4 v = make_float4(0.f, 0.f, 0.f, 0.f);
            if (gr >= 0) v = *(const float4*)(Xp + (size_t)gr * DHD + kc * 64 + f4 * 4);
            int base = row * SA_STRIDE + f4 * 4;
            *(uint4*)(sA + base) = make_uint4(f2tf32(v.x), f2tf32(v.y), f2tf32(v.z), f2tf32(v.w));
        }
        const uint4* bsrc = (const uint4*)(g_Bimg + (size_t)matIdx * 16384 + kc * 8192);
#pragma unroll
        for (int it = 0; it < 8; it++) {
            ((uint4*)sB)[tid + it * 256] = bsrc[tid + it * 256];
        }
        __syncthreads();

#pragma unroll
        for (int kit = 0; kit < 8; kit++) {
            uint32_t ah[2][4];
#pragma unroll
            for (int mt = 0; mt < 2; mt++) {
                int r0 = warp_m * 32 + mt * 16 + (lane >> 2);
                int kk = kit * 8 + (lane & 3);
                ah[mt][0] = sA[r0 * SA_STRIDE + kk];
                ah[mt][1] = sA[(r0 + 8) * SA_STRIDE + kk];
                ah[mt][2] = sA[r0 * SA_STRIDE + kk + 4];
                ah[mt][3] = sA[(r0 + 8) * SA_STRIDE + kk + 4];
            }
#pragma unroll
            for (int nt = 0; nt < 8; nt++) {
                int gnt = warp_n * 8 + nt;
                uint2 b = *(uint2*)(sB + (kit * 16 + gnt) * 64 + lane * 2);
#pragma unroll
                for (int mt = 0; mt < 2; mt++) {
                    mma8(acc[mt][nt], ah[mt], b);
                }
            }
        }
    }
}

#define DECL_ACC(acc)                     \
    float acc[2][8][4];                   \
    _Pragma("unroll") for (int _a = 0; _a < 2; _a++) _Pragma("unroll") for (int _b = 0;        \
                                                                            _b < 8; _b++)      \
        _Pragma("unroll") for (int _c = 0; _c < 4; _c++) acc[_a][_b][_c] = 0.f;

// ---------------- fused Y GEMMs (bf16 output into fused g_Y layout) ----------------
// mode 0: X -> g_Y cols {0,128,256}+ct*?? (convs 0,2,4 at coloff ct*128), with bias
// mode 1: h -> g_Y cols 384+ct*128 (convs 1,3)
// mode 2: rh -> g_yHH (conv 5)
__global__ void __launch_bounds__(256) gemm_y_f(const float* __restrict__ Aext, int mode,
                                                const float* __restrict__ bxz,
                                                const float* __restrict__ bxr,
                                                const float* __restrict__ bxh,
                                                const int* __restrict__ role) {
    extern __shared__ __align__(16) uint32_t sm[];
    __shared__ float sg[DHD * 3];
    __shared__ float bb[DHD * 3];
    __shared__ int role_s[DHD];
    __shared__ int rows[DHD];

    int tid = threadIdx.x, ct = blockIdx.y;
    int r0 = blockIdx.x * DHD;
    const float* Xp = Aext ? Aext : g_rh;

    int conv, ostride, coloff;
    __nv_bfloat16* obase;
    const float* bvec = nullptr;
    if (mode == 0) {
        conv = ct * 2;
        ostride = YW;
        coloff = ct * 128;
        obase = g_Y;
        bvec = (ct == 0) ? bxz : ((ct == 1) ? bxr : bxh);
    } else if (mode == 1) {
        conv = 1 + ct * 2;
        ostride = YW;
        coloff = 384 + ct * 128;
        obase = g_Y;
    } else {
        conv = 5;
        ostride = 128;
        coloff = 0;
        obase = g_yHH;
    }

    for (int t = tid; t < 3 * DHD; t += 256) {
        sg[t] = g_gate[conv * 384 + t];
        bb[t] = bvec ? bvec[t] : 0.0f;
    }
    if (tid < DHD) {
        int gr = r0 + tid;
        rows[tid] = (gr < NN) ? gr : -1;
        role_s[tid] = (gr < NN) ? role[gr] : 0;
    }
    __syncthreads();

    DECL_ACC(acc)
    gemm_mainloop(acc, sm, Xp, rows, conv, tid);

    int lane = tid & 31, wid = tid >> 5;
    int warp_m = wid & 3, warp_n = wid >> 2;
#pragma unroll
    for (int mt = 0; mt < 2; mt++) {
#pragma unroll
        for (int h = 0; h < 2; h++) {
            int lrow = warp_m * 32 + mt * 16 + (lane >> 2) + h * 8;
            int grow = r0 + lrow;
            if (grow >= NN) continue;
            int rb = role_s[lrow] * 128;
            __nv_bfloat16* yp = obase + (size_t)grow * ostride + coloff;
#pragma unroll
            for (int nt = 0; nt < 8; nt++) {
                int col = warp_n * 64 + nt * 8 + (lane & 3) * 2;
                float v0 = acc[mt][nt][h * 2] * sg[rb + col] + bb[rb + col];
                float v1 = acc[mt][nt][h * 2 + 1] * sg[rb + col + 1] + bb[rb + col + 1];
                *(__nv_bfloat162*)(yp + col) = __float22bfloat162_rn(make_float2(v0, v1));
            }
        }
    }
}

// ---------------- fused self GEMMs: buf2 = A[node] @ WS[conv][role] (overwrite) -----
__global__ void __launch_bounds__(256) gemm_self_f(const float* __restrict__ Aext, int mode) {
    int rowBase = blockIdx.x * DHD;
    if (rowBase >= g_rolePadOff[3]) return;
    extern __shared__ __align__(16) uint32_t sm[];
    __shared__ int rows[DHD];

    int tid = threadIdx.x, ct = blockIdx.y;
    const float* Xp = Aext ? Aext : g_rh;

    int r = 0;
    if (rowBase >= g_rolePadOff[1]) r = 1;
    if (rowBase >= g_rolePadOff[2]) r = 2;

    int conv, ostride, coloff;
    float* obase;
    if (mode == 0) { conv = ct * 2; ostride = YW; coloff = ct * 128; obase = g_buf2; }
    else if (mode == 1) { conv = 1 + ct * 2; ostride = YW; coloff = 384 + ct * 128; obase = g_buf2; }
    else { conv = 5; ostride = 128; coloff = 0; obase = g_bufHH2; }
    int matIdx = 6 + conv * 3 + r;

    if (tid < DHD) rows[tid] = (rowBase + tid < PERM_SZ) ? g_perm[rowBase + tid] : -1;
    __syncthreads();

    DECL_ACC(acc)
    gemm_mainloop(acc, sm, Xp, rows, matIdx, tid);

    int lane = tid & 31, wid = tid >> 5;
    int warp_m = wid & 3, warp_n = wid >> 2;
#pragma unroll
    for (int mt = 0; mt < 2; mt++) {
#pragma unroll
        for (int h = 0; h < 2; h++) {
            int lrow = warp_m * 32 + mt * 16 + (lane >> 2) + h * 8;
            int node = rows[lrow];
            if (node < 0) continue;
            float* cp = obase + (size_t)node * ostride + coloff;
#pragma unroll
            for (int nt = 0; nt < 8; nt++) {
                int col = warp_n * 64 + nt * 8 + (lane & 3) * 2;
                *(float2*)(cp + col) =
                    make_float2(acc[mt][nt][h * 2], acc[mt][nt][h * 2 + 1]);
            }
        }
    }
}

// ---------------- fused gathers (warp per node) ----------------
__device__ __forceinline__ void bfacc(float4& a, uint2 u) {
    float2 f0 = __bfloat1622float2(*(__nv_bfloat162*)&u.x);
    float2 f1 = __bfloat1622float2(*(__nv_bfloat162*)&u.y);
    a.x += f0.x; a.y += f0.y; a.z += f1.x; a.w += f1.y;
}
__device__ __forceinline__ float4 scale4(float4 a, float s) {
    return make_float4(a.x * s, a.y * s, a.z * s, a.w * s);
}

// fused gather over g_Y [N,640]: per edge 2x LDG.128 + 1x LDG.64 (was 5x LDG.64).
// Per-column accumulation order identical to the split version -> bit-identical.
__global__ void __launch_bounds__(256) gather_xh_kernel() {
    int w = (blockIdx.x * blockDim.x + threadIdx.x) >> 5;
    int lane = threadIdx.x & 31;
    if (w >= NN) return;
    int s = g_off[w], e = g_off[w + 1];
    float4 a[5];
#pragma unroll
    for (int q = 0; q < 5; q++) a[q] = make_float4(0.f, 0.f, 0.f, 0.f);
    for (int p = s; p < e; p++) {
        int s0 = g_csr[p];
        const char* base = (const char*)(g_Y + (size_t)s0 * YW);
        uint4 uA = *(const uint4*)(base + lane * 16);          // cols [lane*8, lane*8+8)
        uint4 uB = *(const uint4*)(base + 512 + lane * 16);    // cols [256+lane*8, ...)
        uint2 uC = *(const uint2*)(base + 1024 + lane * 8);    // cols [512+lane*4, ...)
        bfacc(a[0], make_uint2(uA.x, uA.y));
        bfacc(a[1], make_uint2(uA.z, uA.w));
        bfacc(a[2], make_uint2(uB.x, uB.y));
        bfacc(a[3], make_uint2(uB.z, uB.w));
        bfacc(a[4], uC);
    }
    float inv = 1.0f / (float)(e - s);
    float* o = g_buf + (size_t)w * YW;
    *(float4*)(o + lane * 8) = scale4(a[0], inv);
    *(float4*)(o + lane * 8 + 4) = scale4(a[1], inv);
    *(float4*)(o + 256 + lane * 8) = scale4(a[2], inv);
    *(float4*)(o + 256 + lane * 8 + 4) = scale4(a[3], inv);
    *(float4*)(o + 512 + lane * 4) = scale4(a[4], inv);
}

// ---------------- combines ----------------
__global__ void combine_zr_kernel(const float* __restrict__ h) {
    size_t idx = (size_t)blockIdx.x * blockDim.x + threadIdx.x;
    if (idx >= (size_t)NN * 32) return;
    size_t i = idx >> 5;
    int q = (int)(idx & 31);
    float4 xz = *(const float4*)(g_buf + i * YW + q * 4);
    float4 xz2 = *(const float4*)(g_buf2 + i * YW + q * 4);
    float4 xr = *(const float4*)(g_buf + i * YW + 128 + q * 4);
    float4 xr2 = *(const float4*)(g_buf2 + i * YW + 128 + q * 4);
    float4 hz = *(const float4*)(g_buf + i * YW + 384 + q * 4);
    float4 hz2 = *(const float4*)(g_buf2 + i * YW + 384 + q * 4);
    float4 hr = *(const float4*)(g_buf + i * YW + 512 + q * 4);
    float4 hr2 = *(const float4*)(g_buf2 + i * YW + 512 + q * 4);
    float4 hv = *(const float4*)(h + i * 128 + q * 4);
    float4 z, rr;
    z.x = sigm(rl(xz.x + xz2.x) + rl(hz.x + hz2.x));
    z.y = sigm(rl(xz.y + xz2.y) + rl(hz.y + hz2.y));
    z.z = sigm(rl(xz.z + xz2.z) + rl(hz.z + hz2.z));
    z.w = sigm(rl(xz.w + xz2.w) + rl(hz.w + hz2.w));
    rr.x = sigm(rl(xr.x + xr2.x) + rl(hr.x + hr2.x)) * hv.x;
    rr.y = sigm(rl(xr.y + xr2.y) + rl(hr.y + hr2.y)) * hv.y;
    rr.z = sigm(rl(xr.z + xr2.z) + rl(hr.z + hr2.z)) * hv.z;
    rr.w = sigm(rl(xr.w + xr2.w) + rl(hr.w + hr2.w)) * hv.w;
    *(float4*)(g_z + i * 128 + q * 4) = z;
    *(float4*)(g_rh + i * 128 + q * 4) = rr;
}

// fused: gather yHH (mean) + final GRU combine, writes out directly.
__global__ void __launch_bounds__(256) gather_hh_combine_kernel(const float* __restrict__ h,
                                                                float* __restrict__ out) {
    int w = (blockIdx.x * blockDim.x + threadIdx.x) >> 5;
    int lane = threadIdx.x & 31;
    if (w >= NN) return;
    int s = g_off[w], e = g_off[w + 1];
    float4 a0 = make_float4(0.f, 0.f, 0.f, 0.f);
    float4 a1 = make_float4(0.f, 0.f, 0.f, 0.f);
    int p = s;
    for (; p + 2 <= e; p += 2) {
        int s0 = g_csr[p], s1v = g_csr[p + 1];
        uint2 u0 = ((const uint2*)(g_yHH + (size_t)s0 * 128))[lane];
        uint2 u1 = ((const uint2*)(g_yHH + (size_t)s1v * 128))[lane];
        bfacc(a0, u0);
        bfacc(a1, u1);
    }
    if (p < e) {
        uint2 u0 = ((const uint2*)(g_yHH + (size_t)g_csr[p] * 128))[lane];
        bfacc(a0, u0);
    }
    float inv = 1.0f / (float)(e - s);
    a0.x += a1.x; a0.y += a1.y; a0.z += a1.z; a0.w += a1.w;
    float4 hh = scale4(a0, inv);

    int col = lane * 4;
    size_t base = (size_t)w * 128 + col;
    float4 hh2 = *(const float4*)(g_bufHH2 + base);
    float4 xh = *(const float4*)(g_buf + (size_t)w * YW + 256 + col);
    float4 xh2 = *(const float4*)(g_buf2 + (size_t)w * YW + 256 + col);
    float4 zv = *(const float4*)(g_z + base);
    float4 hv = *(const float4*)(h + base);
    float4 o;
    float t;
    t = tanhf(rl(xh.x + xh2.x) + rl(hh.x + hh2.x)); o.x = zv.x * hv.x + (1.f - zv.x) * t;
    t = tanhf(rl(xh.y + xh2.y) + rl(hh.y + hh2.y)); o.y = zv.y * hv.y + (1.f - zv.y) * t;
    t = tanhf(rl(xh.z + xh2.z) + rl(hh.z + hh2.z)); o.z = zv.z * hv.z + (1.f - zv.z) * t;
    t = tanhf(rl(xh.w + xh2.w) + rl(hh.w + hh2.w)); o.w = zv.w * hv.w + (1.f - zv.w) * t;
    *(float4*)(out + base) = o;
}

// ---------------- host launch ----------------
extern "C" void kernel_launch(void* const* d_in, const int* in_sizes, int n_in,
                              void* d_out, int out_size) {
    cudaFuncSetAttribute(gemm_y_f, cudaFuncAttributeMaxDynamicSharedMemorySize, GEMM_SMEM);
    cudaFuncSetAttribute(gemm_self_f, cudaFuncAttributeMaxDynamicSharedMemorySize, GEMM_SMEM);

    static cudaStream_t s1 = nullptr;
    static cudaEvent_t evF = nullptr, evA = nullptr, evB = nullptr, evC = nullptr,
                       evD = nullptr, evE = nullptr;
    if (!s1) {
        cudaStreamCreateWithFlags(&s1, cudaStreamNonBlocking);
        cudaEventCreateWithFlags(&evF, cudaEventDisableTiming);
        cudaEventCreateWithFlags(&evA, cudaEventDisableTiming);
        cudaEventCreateWithFlags(&evB, cudaEventDisableTiming);
        cudaEventCreateWithFlags(&evC, cudaEventDisableTiming);
        cudaEventCreateWithFlags(&evD, cudaEventDisableTiming);
        cudaEventCreateWithFlags(&evE, cudaEventDisableTiming);
    }

    int iEdge = 2, iH = 1;
    if (in_sizes[1] == 2 * EE) { iEdge = 1; iH = 2; }
    const float* x = (const float*)d_in[0];
    const float* h_prev = (const float*)d_in[iH];
    const int* ei = (const int*)d_in[iEdge];
    const int* role = (const int*)d_in[3];

    const float* P[27];
    for (int i = 0; i < 27 && (4 + i) < n_in; i++) P[i] = (const float*)d_in[4 + i];
    // xz: W,Wg,bg,S,b = P0..P4 | hz: P5..P8 | xr: P9..P13 | hr: P14..P17
    // xh: P18..P22 | hh: P23..P26
    float* out = (float*)d_out;

    int warpGrid = (NN * 32 + 255) / 256;
    int e4Grid = (ET / 4 + 256) / 256 + 1;

    // ---- Fork 1: CSR build (s1) || weight prep + Y GEMMs (main) ----
    cudaEventRecord(evF, 0);
    cudaStreamWaitEvent(s1, evF, 0);
    init_kernel<<<(PERM_SZ + 255) / 256, 256, 0, s1>>>();
    count_kernel<<<e4Grid, 256, 0, s1>>>(ei, role);
    scan_kernel<<<1, 1024, 0, s1>>>();
    fill_kernel<<<e4Grid, 256, 0, s1>>>(ei, role);
    cudaEventRecord(evA, s1);

    gates_kernel<<<6, 384>>>(P[1], P[2], P[6], P[7], P[10], P[11], P[15], P[16], P[19], P[20],
                             P[24], P[25]);
    ws_all_kernel<<<dim3(4, 3, 6), 256>>>(P[0], P[3], P[5], P[8], P[9], P[12], P[14], P[17],
                                          P[18], P[21], P[23], P[26]);
    img_kernel<<<24, 256>>>(P[0], P[5], P[9], P[14], P[18], P[23]);
    gemm_y_f<<<dim3(RB, 3), 256, GEMM_SMEM>>>(x, 0, P[4], P[13], P[22], role);
    gemm_y_f<<<dim3(RB, 2), 256, GEMM_SMEM>>>(h_prev, 1, nullptr, nullptr, nullptr, role);
    cudaStreamWaitEvent(0, evA, 0);  // join: CSR ready

    // ---- Fork 2: gather (main, critical) || self GEMMs (s1) ----
    cudaEventRecord(evB, 0);
    cudaStreamWaitEvent(s1, evB, 0);
    gemm_self_f<<<dim3(SB, 3), 256, GEMM_SMEM, s1>>>(x, 0);
    gemm_self_f<<<dim3(SB, 2), 256, GEMM_SMEM, s1>>>(h_prev, 1);
    cudaEventRecord(evC, s1);
    gather_xh_kernel<<<warpGrid, 256>>>();
    cudaStreamWaitEvent(0, evC, 0);  // join

    combine_zr_kernel<<<warpGrid, 256>>>(h_prev);

    // ---- Fork 3: self_hh (s1) || yHH GEMM (main); join; fused gather+combine ----
    cudaEventRecord(evD, 0);
    cudaStreamWaitEvent(s1, evD, 0);
    gemm_self_f<<<dim3(SB, 1), 256, GEMM_SMEM, s1>>>(nullptr, 2);
    cudaEventRecord(evE, s1);
    gemm_y_f<<<dim3(RB, 1), 256, GEMM_SMEM>>>(nullptr, 2, nullptr, nullptr, nullptr, role);
    cudaStreamWaitEvent(0, evE, 0);  // join: self_hh done
    gather_hh_combine_kernel<<<warpGrid, 256>>>(h_prev, out);
}